// round 7
// baseline (speedup 1.0000x reference)
#include <cuda_runtime.h>
#include <cstdint>

// GraphProjection. R4 (coalesced scalar) = 90.1us, L1 port ~78% = wavefront
// floor (~182 wf/pt: 120 load + ~62 misaligned store). R5 (ILP) neutral,
// R6 (shfl transpose) regressed on ALU issue. R7: cut port BYTES via
// cross-point reuse — bin points by bilinear cell for levels 3 (14x14) and
// 4 (7x7); a warp owns one cell, keeps the 4 corner rows in registers, and
// serves all its points with zero per-point gather traffic. Coord clipping
// is Cauchy-heavy (~73% clip) so border cells hold thousands of points.

static constexpr int OUT_COLS = 963;
static constexpr int CAP = 1 << 17;  // max supported N for binned path
static constexpr int S3 = 14, C3 = 256, CELLS3 = S3 * S3;
static constexpr int S4 = 7,  C4 = 512, CELLS4 = S4 * S4;

__device__ int g_cnt3[CELLS3];
__device__ int g_cnt4[CELLS4];
__device__ int g_off3[CELLS3 + 1];
__device__ int g_off4[CELLS4 + 1];
__device__ int g_cur3[CELLS3];
__device__ int g_cur4[CELLS4];
__device__ int g_ids3[CAP];
__device__ int g_ids4[CAP];
__device__ float4 g_w3[CAP];
__device__ float4 g_w4[CAP];

__device__ __forceinline__ void project_hw(const float* __restrict__ coord,
                                           int p, float& X, float& Y, float& Z,
                                           float& h, float& w) {
    X = __ldg(coord + 3 * p + 0);
    Y = __ldg(coord + 3 * p + 1);
    Z = __ldg(coord + 3 * p + 2);
    h = 250.0f * (-Y) / (-Z) + 112.0f;
    w = 250.0f * X / (-Z) + 112.0f;
    h = (h < 0.0f) ? 0.0f : ((h > 223.0f) ? 223.0f : h);
    w = (w < 0.0f) ? 0.0f : ((w > 223.0f) ? 223.0f : w);
}

template <int S>
__device__ __forceinline__ int cell_of(float x, float y) {
    int xi = (int)floorf(x);
    int yi = (int)floorf(y);
    if (xi < 0) xi = 0;
    if (yi < 0) yi = 0;
    if (xi > S - 1) xi = S - 1;
    if (yi > S - 1) yi = S - 1;
    return xi * S + yi;
}

template <int S>
__device__ __forceinline__ float4 weights_of(float x, float y) {
    float x1f = floorf(x), x2f = ceilf(x);
    float y1f = floorf(y), y2f = ceilf(y);
    // (w11, w21, w12, w22) exactly as the reference algebra
    return make_float4((x2f - x) * (y2f - y), (x - x1f) * (y2f - y),
                       (x2f - x) * (y - y1f), (x - x1f) * (y - y1f));
}

// ---------- pipeline kernels ----------

__global__ void zero_kernel() {
    int t = threadIdx.x;
    if (t < CELLS3) g_cnt3[t] = 0;
    if (t < CELLS4) g_cnt4[t] = 0;
}

__global__ void count_kernel(const float* __restrict__ coord, int N) {
    int p = blockIdx.x * blockDim.x + threadIdx.x;
    if (p >= N) return;
    float X, Y, Z, h, w;
    project_hw(coord, p, X, Y, Z, h, w);
    atomicAdd(&g_cnt3[cell_of<S3>(h * 0.0625f, w * 0.0625f)], 1);
    atomicAdd(&g_cnt4[cell_of<S4>(h * 0.03125f, w * 0.03125f)], 1);
}

__global__ void scan_kernel() {
    __shared__ int s[256];
    int t = threadIdx.x;
    // level 3
    int v = (t < CELLS3) ? g_cnt3[t] : 0;
    s[t] = v;
    __syncthreads();
    for (int d = 1; d < 256; d <<= 1) {
        int add = (t >= d) ? s[t - d] : 0;
        __syncthreads();
        s[t] += add;
        __syncthreads();
    }
    if (t < CELLS3) {
        g_off3[t + 1] = s[t];
        g_cur3[t] = s[t] - v;  // exclusive
        if (t == 0) g_off3[0] = 0;
    }
    __syncthreads();
    // level 4
    int v4 = (t < CELLS4) ? g_cnt4[t] : 0;
    s[t] = v4;
    __syncthreads();
    for (int d = 1; d < 256; d <<= 1) {
        int add = (t >= d) ? s[t - d] : 0;
        __syncthreads();
        s[t] += add;
        __syncthreads();
    }
    if (t < CELLS4) {
        g_off4[t + 1] = s[t];
        g_cur4[t] = s[t] - v4;
        if (t == 0) g_off4[0] = 0;
    }
}

__global__ void scatter_kernel(const float* __restrict__ coord, int N) {
    int p = blockIdx.x * blockDim.x + threadIdx.x;
    if (p >= N) return;
    float X, Y, Z, h, w;
    project_hw(coord, p, X, Y, Z, h, w);
    {
        float x = h * 0.0625f, y = w * 0.0625f;
        int pos = atomicAdd(&g_cur3[cell_of<S3>(x, y)], 1);
        g_ids3[pos] = p;
        g_w3[pos] = weights_of<S3>(x, y);
    }
    {
        float x = h * 0.03125f, y = w * 0.03125f;
        int pos = atomicAdd(&g_cur4[cell_of<S4>(x, y)], 1);
        g_ids4[pos] = p;
        g_w4[pos] = weights_of<S4>(x, y);
    }
}

// Cell-gather: warp owns one cell's 4 corner rows in registers, streams its
// binned points. LVL selects the global bin structures at compile time.
template <int C, int S, int LVL, int COLBASE>
__global__ void __launch_bounds__(256)
cell_gather_kernel(const float* __restrict__ feat, float* __restrict__ out) {
    const int* off = (LVL == 3) ? g_off3 : g_off4;
    const int* ids = (LVL == 3) ? g_ids3 : g_ids4;
    const float4* wts = (LVL == 3) ? g_w3 : g_w4;

    int cell = blockIdx.x;
    int base = __ldg(off + cell);
    int cnt = __ldg(off + cell + 1) - base;
    if (cnt == 0) return;

    int wid = threadIdx.x >> 5;
    int lane = threadIdx.x & 31;
    int wstride = gridDim.y * (blockDim.x >> 5);
    int i0 = blockIdx.y * (blockDim.x >> 5) + wid;
    if (i0 >= cnt) return;

    int r1 = cell / S, c1 = cell % S;
    int r2 = (r1 + 1 < S) ? r1 + 1 : S - 1;
    int c2 = (c1 + 1 < S) ? c1 + 1 : S - 1;
    const float* p11 = feat + (r1 * S + c1) * C;
    const float* p21 = feat + (r2 * S + c1) * C;
    const float* p12 = feat + (r1 * S + c2) * C;
    const float* p22 = feat + (r2 * S + c2) * C;

    float R11[C / 32], R21[C / 32], R12[C / 32], R22[C / 32];
#pragma unroll
    for (int j = 0; j < C / 32; ++j) {
        R11[j] = __ldg(p11 + lane + 32 * j);
        R21[j] = __ldg(p21 + lane + 32 * j);
        R12[j] = __ldg(p12 + lane + 32 * j);
        R22[j] = __ldg(p22 + lane + 32 * j);
    }

    for (int i = i0; i < cnt; i += wstride) {
        int pid = __ldg(ids + base + i);
        float4 w = __ldg(wts + base + i);
        float* __restrict__ o = out + (size_t)pid * OUT_COLS + COLBASE;
#pragma unroll
        for (int j = 0; j < C / 32; ++j)
            o[lane + 32 * j] =
                w.x * R11[j] + w.y * R21[j] + w.z * R12[j] + w.w * R22[j];
    }
}

// ---------- per-point scalar bilerp (levels 1,2 + fallback) ----------

template <int C, int S>
__device__ __forceinline__ void bilerp_scalar(const float* __restrict__ feat,
                                              float x, float y,
                                              float* __restrict__ o, int lane) {
    float x1f = floorf(x), x2f = ceilf(x);
    float y1f = floorf(y), y2f = ceilf(y);
    int xi1 = (int)x1f, xi2 = (int)x2f, yi1 = (int)y1f, yi2 = (int)y2f;
    if (xi1 < 0) xi1 = 0;
    if (yi1 < 0) yi1 = 0;
    if (xi2 < 0) xi2 = 0;
    if (yi2 < 0) yi2 = 0;
    if (xi1 > S - 1) xi1 = S - 1;
    if (yi1 > S - 1) yi1 = S - 1;
    if (xi2 > S - 1) xi2 = S - 1;
    if (yi2 > S - 1) yi2 = S - 1;
    float w11 = (x2f - x) * (y2f - y);
    float w21 = (x - x1f) * (y2f - y);
    float w12 = (x2f - x) * (y - y1f);
    float w22 = (x - x1f) * (y - y1f);
    const float* Q11 = feat + (xi1 * S + yi1) * C;
    const float* Q21 = feat + (xi2 * S + yi1) * C;
    const float* Q12 = feat + (xi1 * S + yi2) * C;
    const float* Q22 = feat + (xi2 * S + yi2) * C;
#pragma unroll
    for (int i = 0; i < C / 32; ++i) {
        int c = lane + 32 * i;
        float a = __ldg(Q11 + c);
        float b = __ldg(Q21 + c);
        float cc = __ldg(Q12 + c);
        float d = __ldg(Q22 + c);
        o[c] = w11 * a + w21 * b + w12 * cc + w22 * d;
    }
}

// base kernel: coord + levels 1,2 (cols [0,195))
__global__ void __launch_bounds__(256)
base_kernel(const float* __restrict__ coord, const float* __restrict__ f1,
            const float* __restrict__ f2, float* __restrict__ out, int N) {
    int p = (blockIdx.x * blockDim.x + threadIdx.x) >> 5;
    int lane = threadIdx.x & 31;
    if (p >= N) return;
    float X, Y, Z, h, w;
    project_hw(coord, p, X, Y, Z, h, w);
    float* __restrict__ orow = out + (size_t)p * OUT_COLS;
    if (lane == 0) orow[0] = X;
    if (lane == 1) orow[1] = Y;
    if (lane == 2) orow[2] = Z;
    bilerp_scalar<64, 56>(f1, h * 0.25f, w * 0.25f, orow + 3, lane);
    bilerp_scalar<128, 28>(f2, h * 0.125f, w * 0.125f, orow + 67, lane);
}

// fallback: full per-point kernel (N > CAP)
__global__ void __launch_bounds__(256)
full_kernel(const float* __restrict__ coord, const float* __restrict__ f1,
            const float* __restrict__ f2, const float* __restrict__ f3,
            const float* __restrict__ f4, float* __restrict__ out, int N) {
    int p = (blockIdx.x * blockDim.x + threadIdx.x) >> 5;
    int lane = threadIdx.x & 31;
    if (p >= N) return;
    float X, Y, Z, h, w;
    project_hw(coord, p, X, Y, Z, h, w);
    float* __restrict__ orow = out + (size_t)p * OUT_COLS;
    if (lane == 0) orow[0] = X;
    if (lane == 1) orow[1] = Y;
    if (lane == 2) orow[2] = Z;
    bilerp_scalar<64, 56>(f1, h * 0.25f, w * 0.25f, orow + 3, lane);
    bilerp_scalar<128, 28>(f2, h * 0.125f, w * 0.125f, orow + 67, lane);
    bilerp_scalar<256, 14>(f3, h * 0.0625f, w * 0.0625f, orow + 195, lane);
    bilerp_scalar<512, 7>(f4, h * 0.03125f, w * 0.03125f, orow + 451, lane);
}

extern "C" void kernel_launch(void* const* d_in, const int* in_sizes, int n_in,
                              void* d_out, int out_size) {
    const float* coord = (const float*)d_in[0];
    const float* f1 = (const float*)d_in[1];
    const float* f2 = (const float*)d_in[2];
    const float* f3 = (const float*)d_in[3];
    const float* f4 = (const float*)d_in[4];
    float* out = (float*)d_out;

    int N = in_sizes[0] / 3;

    if (N > CAP) {
        full_kernel<<<(N + 7) / 8, 256>>>(coord, f1, f2, f3, f4, out, N);
        return;
    }

    int pb = (N + 255) / 256;
    zero_kernel<<<1, 256>>>();
    count_kernel<<<pb, 256>>>(coord, N);
    scan_kernel<<<1, 256>>>();
    scatter_kernel<<<pb, 256>>>(coord, N);

    // independent of binning order beyond stream ordering:
    base_kernel<<<(N + 7) / 8, 256>>>(coord, f1, f2, out, N);
    // level 3: 196 cells x 32 splits; level 4: 49 cells x 64 splits
    cell_gather_kernel<C3, S3, 3, 195><<<dim3(CELLS3, 32), 256>>>(f3, out);
    cell_gather_kernel<C4, S4, 4, 451><<<dim3(CELLS4, 64), 256>>>(f4, out);
}

// round 8
// speedup vs baseline: 3.0617x; 3.0617x over previous
#include <cuda_runtime.h>
#include <cstdint>

// GraphProjection, monolithic (R7 binning abandoned: global-atomic
// serialization + lost DRAM/port overlap).
// Model: port-bound. wf/pt: 120 load (byte floor) + stores. R4's STG.32 at
// 4B-aligned rows = 62 store wf. R8: all level bases are ==3 mod 4 =>
// single per-point shift t makes o+t 16B-aligned for every level; store
// words built from own LDG.128-blend word + <=3 shfl'd comps of next word.
// Static 4-way branch on warp-uniform t => no dynamic selects.

static constexpr int OUT_COLS = 963;

struct Corners {
    const float* Q11;
    const float* Q21;
    const float* Q12;
    const float* Q22;
    float w11, w21, w12, w22;
};

template <int C, int S>
__device__ __forceinline__ Corners prep(const float* __restrict__ feat,
                                        float x, float y) {
    float x1f = floorf(x), x2f = ceilf(x);
    float y1f = floorf(y), y2f = ceilf(y);
    int xi1 = (int)x1f, xi2 = (int)x2f, yi1 = (int)y1f, yi2 = (int)y2f;
    if (xi1 < 0) xi1 = 0;
    if (yi1 < 0) yi1 = 0;
    if (xi2 < 0) xi2 = 0;
    if (yi2 < 0) yi2 = 0;
    if (xi1 > S - 1) xi1 = S - 1;
    if (yi1 > S - 1) yi1 = S - 1;
    if (xi2 > S - 1) xi2 = S - 1;
    if (yi2 > S - 1) yi2 = S - 1;
    Corners t;
    t.w11 = (x2f - x) * (y2f - y);
    t.w21 = (x - x1f) * (y2f - y);
    t.w12 = (x2f - x) * (y - y1f);
    t.w22 = (x - x1f) * (y - y1f);
    t.Q11 = feat + (xi1 * S + yi1) * C;
    t.Q21 = feat + (xi2 * S + yi1) * C;
    t.Q12 = feat + (xi1 * S + yi2) * C;
    t.Q22 = feat + (xi2 * S + yi2) * C;
    return t;
}

// Store with compile-time shift T (1..3): word at o+T+4w = comps T..3 of
// blend-word w plus comps 0..T-1 of blend-word w+1 (shfl from lane+1; the
// lane31 straddle word comes from lane0's next r[] via a second shfl).
template <int T, int ITERS>
__device__ __forceinline__ void store_shift(float* __restrict__ o,
                                            const float4* r, int lane) {
    constexpr int WORDS = 32 * ITERS - 1;  // floor((128*ITERS - T)/4)
    if (lane == 0) {
        o[0] = r[0].x;
        if (T > 1) o[1] = r[0].y;
        if (T > 2) o[2] = r[0].z;
    }
#pragma unroll
    for (int i = 0; i < ITERS; ++i) {
        float4 rn = (i + 1 < ITERS) ? r[i + 1] : r[i];  // dummy on last iter
        int src = (lane + 1) & 31;
        float n0 = 0.f, n1 = 0.f, n2 = 0.f;
        {
            float a = __shfl_sync(0xffffffffu, r[i].x, src);
            float b = __shfl_sync(0xffffffffu, rn.x, src);
            n0 = (lane == 31) ? b : a;
        }
        if (T > 1) {
            float a = __shfl_sync(0xffffffffu, r[i].y, src);
            float b = __shfl_sync(0xffffffffu, rn.y, src);
            n1 = (lane == 31) ? b : a;
        }
        if (T > 2) {
            float a = __shfl_sync(0xffffffffu, r[i].z, src);
            float b = __shfl_sync(0xffffffffu, rn.z, src);
            n2 = (lane == 31) ? b : a;
        }
        float4 sv;
        if (T == 1) sv = make_float4(r[i].y, r[i].z, r[i].w, n0);
        if (T == 2) sv = make_float4(r[i].z, r[i].w, n0, n1);
        if (T == 3) sv = make_float4(r[i].w, n0, n1, n2);
        int wp = lane + 32 * i;
        if (wp < WORDS) ((float4*)(o + T))[wp] = sv;
    }
    if (lane == 31) {  // tail comps T..3 of last word -> channels C-4+T..C-1
        constexpr int CB = ITERS * 128;
        o[CB - 1] = r[ITERS - 1].w;
        if (T <= 2) o[CB - 2] = r[ITERS - 1].z;
        if (T <= 1) o[CB - 3] = r[ITERS - 1].y;
    }
}

template <int C, int S>
__device__ __forceinline__ void bilerp_vec(const float* __restrict__ feat,
                                           float x, float y,
                                           float* __restrict__ o,
                                           int lane, int t) {
    Corners cx = prep<C, S>(feat, x, y);
    const float4* P11 = (const float4*)cx.Q11;
    const float4* P21 = (const float4*)cx.Q21;
    const float4* P12 = (const float4*)cx.Q12;
    const float4* P22 = (const float4*)cx.Q22;

    constexpr int ITERS = C / 128;
    float4 r[ITERS];
#pragma unroll
    for (int i = 0; i < ITERS; ++i) {
        int wd = lane + 32 * i;
        float4 a = __ldg(P11 + wd);
        float4 b = __ldg(P21 + wd);
        float4 c = __ldg(P12 + wd);
        float4 d = __ldg(P22 + wd);
        r[i].x = cx.w11 * a.x + cx.w21 * b.x + cx.w12 * c.x + cx.w22 * d.x;
        r[i].y = cx.w11 * a.y + cx.w21 * b.y + cx.w12 * c.y + cx.w22 * d.y;
        r[i].z = cx.w11 * a.z + cx.w21 * b.z + cx.w12 * c.z + cx.w22 * d.z;
        r[i].w = cx.w11 * a.w + cx.w21 * b.w + cx.w12 * c.w + cx.w22 * d.w;
    }

    if (t == 0) {
#pragma unroll
        for (int i = 0; i < ITERS; ++i)
            ((float4*)o)[lane + 32 * i] = r[i];
    } else if (t == 1) {
        store_shift<1, ITERS>(o, r, lane);
    } else if (t == 2) {
        store_shift<2, ITERS>(o, r, lane);
    } else {
        store_shift<3, ITERS>(o, r, lane);
    }
}

// Level 1 (C=64): small; scalar coalesced path.
template <int C, int S>
__device__ __forceinline__ void bilerp_scalar(const float* __restrict__ feat,
                                              float x, float y,
                                              float* __restrict__ o, int lane) {
    Corners t = prep<C, S>(feat, x, y);
#pragma unroll
    for (int i = 0; i < C / 32; ++i) {
        int c = lane + 32 * i;
        float a = __ldg(t.Q11 + c);
        float b = __ldg(t.Q21 + c);
        float cc = __ldg(t.Q12 + c);
        float d = __ldg(t.Q22 + c);
        o[c] = t.w11 * a + t.w21 * b + t.w12 * cc + t.w22 * d;
    }
}

__global__ void __launch_bounds__(256)
graph_projection_kernel(const float* __restrict__ coord,
                        const float* __restrict__ f1,
                        const float* __restrict__ f2,
                        const float* __restrict__ f3,
                        const float* __restrict__ f4,
                        float* __restrict__ out, int N) {
    int p = (blockIdx.x * blockDim.x + threadIdx.x) >> 5;  // warp = point
    int lane = threadIdx.x & 31;
    if (p >= N) return;

    float X = __ldg(coord + 3 * p + 0);
    float Y = __ldg(coord + 3 * p + 1);
    float Z = __ldg(coord + 3 * p + 2);

    float h = 250.0f * (-Y) / (-Z) + 112.0f;
    float w = 250.0f * X / (-Z) + 112.0f;
    h = (h < 0.0f) ? 0.0f : ((h > 223.0f) ? 223.0f : h);
    w = (w < 0.0f) ? 0.0f : ((w > 223.0f) ? 223.0f : w);

    float* __restrict__ orow = out + (size_t)p * OUT_COLS;
    if (lane == 0) orow[0] = X;
    if (lane == 1) orow[1] = Y;
    if (lane == 2) orow[2] = Z;

    // shift making (orow + base + t) 16B-aligned; all bases == 3 mod 4
    int m = (p * 963 + 3) & 3;
    int t = (4 - m) & 3;

    bilerp_scalar<64, 56>(f1, h * 0.25f, w * 0.25f, orow + 3, lane);
    bilerp_vec<128, 28>(f2, h * 0.125f, w * 0.125f, orow + 67, lane, t);
    bilerp_vec<256, 14>(f3, h * 0.0625f, w * 0.0625f, orow + 195, lane, t);
    bilerp_vec<512, 7>(f4, h * 0.03125f, w * 0.03125f, orow + 451, lane, t);
}

extern "C" void kernel_launch(void* const* d_in, const int* in_sizes, int n_in,
                              void* d_out, int out_size) {
    const float* coord = (const float*)d_in[0];
    const float* f1 = (const float*)d_in[1];
    const float* f2 = (const float*)d_in[2];
    const float* f3 = (const float*)d_in[3];
    const float* f4 = (const float*)d_in[4];
    float* out = (float*)d_out;

    int N = in_sizes[0] / 3;

    int blocks = (N + 7) / 8;  // 8 warps/block, 1 point/warp
    graph_projection_kernel<<<blocks, 256>>>(coord, f1, f2, f3, f4, out, N);
}

// round 9
// speedup vs baseline: 3.8752x; 1.2657x over previous
#include <cuda_runtime.h>
#include <cstdint>

// GraphProjection, monolithic. History:
//  R4 coalesced scalar: 90.1us (L1 port-bound, ~182 wf/pt).
//  R5 2pt-ILP neutral; R6 shfl transpose regressed (ALU);
//  R8 shfl store-shift neutral (SHFL eats the same MIO/L1 pipe as STG).
// R9: math shortcut. h,w derive from a Cauchy ratio; ~36% clip to 0 each.
// h==0 => x=h/scale=0 integral at EVERY level => (x2-x)=(x-x1)=0 => all four
// bilinear weights are exactly 0 => the whole 960-channel feature block is
// exactly 0.0f (same for w==0). ~59% of points skip all gather loads and
// just zero-fill. Exact: ref sums of signed zeros differ at most in zero
// sign (rel-err 0); NaN h/w fails ==0 and takes the general path.

static constexpr int OUT_COLS = 963;

template <int C, int S>
__device__ __forceinline__ void bilerp_scalar(const float* __restrict__ feat,
                                              float x, float y,
                                              float* __restrict__ o, int lane) {
    float x1f = floorf(x), x2f = ceilf(x);
    float y1f = floorf(y), y2f = ceilf(y);
    int xi1 = (int)x1f, xi2 = (int)x2f, yi1 = (int)y1f, yi2 = (int)y2f;
    // JAX gather clamps; lower clamp also guards NaN->int conversion.
    if (xi1 < 0) xi1 = 0;
    if (yi1 < 0) yi1 = 0;
    if (xi2 < 0) xi2 = 0;
    if (yi2 < 0) yi2 = 0;
    if (xi1 > S - 1) xi1 = S - 1;
    if (yi1 > S - 1) yi1 = S - 1;
    if (xi2 > S - 1) xi2 = S - 1;
    if (yi2 > S - 1) yi2 = S - 1;

    float w11 = (x2f - x) * (y2f - y);
    float w21 = (x - x1f) * (y2f - y);
    float w12 = (x2f - x) * (y - y1f);
    float w22 = (x - x1f) * (y - y1f);

    const float* Q11 = feat + (xi1 * S + yi1) * C;
    const float* Q21 = feat + (xi2 * S + yi1) * C;
    const float* Q12 = feat + (xi1 * S + yi2) * C;
    const float* Q22 = feat + (xi2 * S + yi2) * C;

#pragma unroll
    for (int i = 0; i < C / 32; ++i) {
        int c = lane + 32 * i;
        float a = __ldg(Q11 + c);
        float b = __ldg(Q21 + c);
        float cc = __ldg(Q12 + c);
        float d = __ldg(Q22 + c);
        o[c] = w11 * a + w21 * b + w12 * cc + w22 * d;
    }
}

__global__ void __launch_bounds__(256)
graph_projection_kernel(const float* __restrict__ coord,
                        const float* __restrict__ f1,
                        const float* __restrict__ f2,
                        const float* __restrict__ f3,
                        const float* __restrict__ f4,
                        float* __restrict__ out, int N) {
    int p = (blockIdx.x * blockDim.x + threadIdx.x) >> 5;  // warp = point
    int lane = threadIdx.x & 31;
    if (p >= N) return;

    float X = __ldg(coord + 3 * p + 0);
    float Y = __ldg(coord + 3 * p + 1);
    float Z = __ldg(coord + 3 * p + 2);

    float h = 250.0f * (-Y) / (-Z) + 112.0f;
    float w = 250.0f * X / (-Z) + 112.0f;
    // clip to [0,223]; comparison form preserves jnp.clip NaN propagation
    h = (h < 0.0f) ? 0.0f : ((h > 223.0f) ? 223.0f : h);
    w = (w < 0.0f) ? 0.0f : ((w > 223.0f) ? 223.0f : w);

    float* __restrict__ orow = out + (size_t)p * OUT_COLS;
    if (lane == 0) orow[0] = X;
    if (lane == 1) orow[1] = Y;
    if (lane == 2) orow[2] = Z;

    // Fast path: h==0 or w==0 => integral grid coordinate at every level =>
    // all bilinear weights exactly zero => 960-channel block is exactly 0.
    if (h == 0.0f || w == 0.0f) {
#pragma unroll
        for (int i = 0; i < 30; ++i)
            orow[3 + lane + 32 * i] = 0.0f;
        return;
    }

    // scales: 224/56=4, 224/28=8, 224/14=16, 224/7=32 (exact pow2 -> mul ok)
    bilerp_scalar<64, 56>(f1, h * 0.25f,    w * 0.25f,    orow + 3,   lane);
    bilerp_scalar<128, 28>(f2, h * 0.125f,  w * 0.125f,   orow + 67,  lane);
    bilerp_scalar<256, 14>(f3, h * 0.0625f, w * 0.0625f,  orow + 195, lane);
    bilerp_scalar<512, 7>(f4, h * 0.03125f, w * 0.03125f, orow + 451, lane);
}

extern "C" void kernel_launch(void* const* d_in, const int* in_sizes, int n_in,
                              void* d_out, int out_size) {
    const float* coord = (const float*)d_in[0];
    const float* f1 = (const float*)d_in[1];
    const float* f2 = (const float*)d_in[2];
    const float* f3 = (const float*)d_in[3];
    const float* f4 = (const float*)d_in[4];
    float* out = (float*)d_out;

    int N = in_sizes[0] / 3;

    int blocks = (N + 7) / 8;  // 8 warps/block, 1 point/warp
    graph_projection_kernel<<<blocks, 256>>>(coord, f1, f2, f3, f4, out, N);
}

// round 10
// speedup vs baseline: 3.9660x; 1.0234x over previous
#include <cuda_runtime.h>
#include <cstdint>

// GraphProjection, monolithic. History:
//  R4 coalesced scalar: 90.1us (L1 port-bound ~182 wf/pt).
//  R5 ILP neutral; R6 shfl transpose regressed; R8 shfl store-shift neutral
//  (SHFL shares the MIO/L1 pipe with STG).
//  R9 Cauchy-clip zero shortcut (h==0 || w==0 => all bilinear weights exactly
//  0 at every level => 960-ch block exactly 0): 71.3us, DRAM 56.6%.
// R10: the zero-fill carries no data, so align it for free: head scalars to
// the 16B boundary, STG.128 zeros, tail scalars. Fast-path store wavefronts
// ~60 -> ~31 (line-minimal). Slow path untouched.

static constexpr int OUT_COLS = 963;

template <int C, int S>
__device__ __forceinline__ void bilerp_scalar(const float* __restrict__ feat,
                                              float x, float y,
                                              float* __restrict__ o, int lane) {
    float x1f = floorf(x), x2f = ceilf(x);
    float y1f = floorf(y), y2f = ceilf(y);
    int xi1 = (int)x1f, xi2 = (int)x2f, yi1 = (int)y1f, yi2 = (int)y2f;
    // JAX gather clamps; lower clamp also guards NaN->int conversion.
    if (xi1 < 0) xi1 = 0;
    if (yi1 < 0) yi1 = 0;
    if (xi2 < 0) xi2 = 0;
    if (yi2 < 0) yi2 = 0;
    if (xi1 > S - 1) xi1 = S - 1;
    if (yi1 > S - 1) yi1 = S - 1;
    if (xi2 > S - 1) xi2 = S - 1;
    if (yi2 > S - 1) yi2 = S - 1;

    float w11 = (x2f - x) * (y2f - y);
    float w21 = (x - x1f) * (y2f - y);
    float w12 = (x2f - x) * (y - y1f);
    float w22 = (x - x1f) * (y - y1f);

    const float* Q11 = feat + (xi1 * S + yi1) * C;
    const float* Q21 = feat + (xi2 * S + yi1) * C;
    const float* Q12 = feat + (xi1 * S + yi2) * C;
    const float* Q22 = feat + (xi2 * S + yi2) * C;

#pragma unroll
    for (int i = 0; i < C / 32; ++i) {
        int c = lane + 32 * i;
        float a = __ldg(Q11 + c);
        float b = __ldg(Q21 + c);
        float cc = __ldg(Q12 + c);
        float d = __ldg(Q22 + c);
        o[c] = w11 * a + w21 * b + w12 * cc + w22 * d;
    }
}

__global__ void __launch_bounds__(256)
graph_projection_kernel(const float* __restrict__ coord,
                        const float* __restrict__ f1,
                        const float* __restrict__ f2,
                        const float* __restrict__ f3,
                        const float* __restrict__ f4,
                        float* __restrict__ out, int N) {
    int p = (blockIdx.x * blockDim.x + threadIdx.x) >> 5;  // warp = point
    int lane = threadIdx.x & 31;
    if (p >= N) return;

    float X = __ldg(coord + 3 * p + 0);
    float Y = __ldg(coord + 3 * p + 1);
    float Z = __ldg(coord + 3 * p + 2);

    float h = 250.0f * (-Y) / (-Z) + 112.0f;
    float w = 250.0f * X / (-Z) + 112.0f;
    // clip to [0,223]; comparison form preserves jnp.clip NaN propagation
    h = (h < 0.0f) ? 0.0f : ((h > 223.0f) ? 223.0f : h);
    w = (w < 0.0f) ? 0.0f : ((w > 223.0f) ? 223.0f : w);

    float* __restrict__ orow = out + (size_t)p * OUT_COLS;
    if (lane == 0) orow[0] = X;
    if (lane == 1) orow[1] = Y;
    if (lane == 2) orow[2] = Z;

    // Fast path: h==0 or w==0 => x=h/scale integral at every level =>
    // (x2-x)=(x-x1)=0 => all four weights exactly 0 => 960-ch block = 0.
    if (h == 0.0f || w == 0.0f) {
        float* z = orow + 3;  // 960 floats to zero
        // floats until 16B alignment (z is 4B aligned)
        int head = (int)(((16u - ((uint32_t)(uintptr_t)z & 15u)) & 15u) >> 2);
        if (lane < head) z[lane] = 0.0f;
        int nvec = (960 - head) >> 2;  // 239 or 240 float4 words
        float4* v = (float4*)(z + head);
        float4 z4 = make_float4(0.f, 0.f, 0.f, 0.f);
#pragma unroll
        for (int i = 0; i < 8; ++i) {
            int idx = lane + 32 * i;
            if (idx < nvec) v[idx] = z4;
        }
        int done = head + 4 * nvec;
        if (lane < 960 - done) z[done + lane] = 0.0f;
        return;
    }

    // scales: 224/56=4, 224/28=8, 224/14=16, 224/7=32 (exact pow2 -> mul ok)
    bilerp_scalar<64, 56>(f1, h * 0.25f,    w * 0.25f,    orow + 3,   lane);
    bilerp_scalar<128, 28>(f2, h * 0.125f,  w * 0.125f,   orow + 67,  lane);
    bilerp_scalar<256, 14>(f3, h * 0.0625f, w * 0.0625f,  orow + 195, lane);
    bilerp_scalar<512, 7>(f4, h * 0.03125f, w * 0.03125f, orow + 451, lane);
}

extern "C" void kernel_launch(void* const* d_in, const int* in_sizes, int n_in,
                              void* d_out, int out_size) {
    const float* coord = (const float*)d_in[0];
    const float* f1 = (const float*)d_in[1];
    const float* f2 = (const float*)d_in[2];
    const float* f3 = (const float*)d_in[3];
    const float* f4 = (const float*)d_in[4];
    float* out = (float*)d_out;

    int N = in_sizes[0] / 3;

    int blocks = (N + 7) / 8;  // 8 warps/block, 1 point/warp
    graph_projection_kernel<<<blocks, 256>>>(coord, f1, f2, f3, f4, out, N);
}